// round 9
// baseline (speedup 1.0000x reference)
#include <cuda_runtime.h>
#include <cstdint>
#include <math.h>

// Problem dims (fixed by the reference)
#define TDIM 4096
#define CDIM 2048
#define NF   2048
#define N3   6144   // 3*NF

#define BM 128
#define BN 128
#define BK 32
#define SA 36    // A-style tile stride in floats ([row][k]), conflict-free
#define SB 136   // B NN tile stride in floats ([k][n]), conflict-free

// Scratch (fp32, pre-rounded to tf32 grid).
// g_xr / g_wt: K dim permuted in 16-groups (j -> 4*(j%4)+j/4, an involution).
// g_qkv: Q and K feature columns permuted the same way; V columns original.
__device__ __align__(256) float g_qkv[(size_t)TDIM * N3];
__device__ __align__(256) float g_P[(size_t)TDIM * TDIM];
__device__ __align__(256) float g_xr[(size_t)TDIM * CDIM];
__device__ __align__(256) float g_wt[(size_t)N3 * CDIM];    // W^T [n][k], k permuted

__device__ __forceinline__ float f2tf32f(float x) {
    uint32_t u;
    asm("cvt.rna.tf32.f32 %0, %1;" : "=r"(u) : "f"(x));
    return __uint_as_float(u);
}

__device__ __forceinline__ void mma_tf32(float* d,
    uint32_t a0, uint32_t a1, uint32_t a2, uint32_t a3,
    uint32_t b0, uint32_t b1)
{
    asm volatile(
        "mma.sync.aligned.m16n8k8.row.col.f32.tf32.tf32.f32 "
        "{%0,%1,%2,%3}, {%4,%5,%6,%7}, {%8,%9}, {%0,%1,%2,%3};\n"
        : "+f"(d[0]), "+f"(d[1]), "+f"(d[2]), "+f"(d[3])
        : "r"(a0), "r"(a1), "r"(a2), "r"(a3), "r"(b0), "r"(b1));
}

__device__ __forceinline__ void cp16(float* smem_dst, const float* gsrc) {
    uint32_t s = (uint32_t)__cvta_generic_to_shared(smem_dst);
    asm volatile("cp.async.cg.shared.global [%0], [%1], 16;\n" :: "r"(s), "l"(gsrc));
}
#define CP_COMMIT() asm volatile("cp.async.commit_group;\n")
#define CP_WAIT0()  asm volatile("cp.async.wait_group 0;\n")

// permuted position of absolute column/index f (16-group involution)
__device__ __forceinline__ int perm16(int f) {
    int j = f & 15;
    return (f & ~15) + 4 * (j & 3) + (j >> 2);
}

// Async-copy a 128x32 fp32 tile (row pitch ld) into tile[row][k], stride SA.
__device__ __forceinline__ void loadA_async(float* tile, const float* __restrict__ src,
                                            size_t ld, int tid)
{
    #pragma unroll
    for (int i = 0; i < 4; i++) {
        int idx = tid + i * 256;
        int r = idx >> 3;
        int k = (idx & 7) << 2;
        cp16(tile + r * SA + k, src + (size_t)r * ld + k);
    }
}

// Async-copy a 32x128 fp32 tile (row pitch ld) into tile[k][n], stride SB.
__device__ __forceinline__ void loadB_async(float* tile, const float* __restrict__ src,
                                            size_t ld, int tid)
{
    #pragma unroll
    for (int i = 0; i < 4; i++) {
        int idx = tid + i * 256;
        int k = idx >> 5;
        int n = (idx & 31) << 2;
        cp16(tile + k * SB + n, src + (size_t)k * ld + n);
    }
}

// ---------------------------------------------------------------------------
// Vectorized NT compute: both tiles [row][k] stride SA, K pre-permuted in
// 16-groups. One LDS.128 per row feeds TWO k8 MMA steps.
// ---------------------------------------------------------------------------
__device__ __forceinline__ void compute_NT_vec(const float* As, const float* Bs,
                                               float (*acc)[4], int wm, int wn, int g, int t4)
{
    #pragma unroll
    for (int q = 0; q < 2; q++) {
        const int kb16 = q * 16 + 4 * t4;
        float4 bv[4];
        #pragma unroll
        for (int nt = 0; nt < 4; nt++) {
            const int n = wn * 32 + nt * 8 + g;
            bv[nt] = *(const float4*)&Bs[n * SA + kb16];
        }
        #pragma unroll
        for (int mt = 0; mt < 4; mt++) {
            const int m = wm * 64 + mt * 16 + g;
            float4 a0 = *(const float4*)&As[m * SA + kb16];
            float4 a1 = *(const float4*)&As[(m + 8) * SA + kb16];
            #pragma unroll
            for (int nt = 0; nt < 4; nt++)
                mma_tf32(acc[mt * 4 + nt],
                         __float_as_uint(a0.x), __float_as_uint(a1.x),
                         __float_as_uint(a0.y), __float_as_uint(a1.y),
                         __float_as_uint(bv[nt].x), __float_as_uint(bv[nt].y));
            #pragma unroll
            for (int nt = 0; nt < 4; nt++)
                mma_tf32(acc[mt * 4 + nt],
                         __float_as_uint(a0.z), __float_as_uint(a1.z),
                         __float_as_uint(a0.w), __float_as_uint(a1.w),
                         __float_as_uint(bv[nt].z), __float_as_uint(bv[nt].w));
        }
    }
}

// Scalar NN compute (round-4 path, used by PV): B tile [k][n] stride SB.
__device__ __forceinline__ void compute_NN(const float* As, const float* Bs,
                                           float (*acc)[4], int wm, int wn, int g, int t4)
{
    #pragma unroll
    for (int ks = 0; ks < 4; ks++) {
        const int kb = ks * 8;
        uint32_t af[4][4], bf[4][2];
        #pragma unroll
        for (int mt = 0; mt < 4; mt++) {
            const int m = wm * 64 + mt * 16 + g;
            af[mt][0] = __float_as_uint(As[m * SA + kb + t4]);
            af[mt][1] = __float_as_uint(As[(m + 8) * SA + kb + t4]);
            af[mt][2] = __float_as_uint(As[m * SA + kb + t4 + 4]);
            af[mt][3] = __float_as_uint(As[(m + 8) * SA + kb + t4 + 4]);
        }
        #pragma unroll
        for (int nt = 0; nt < 4; nt++) {
            const int n = wn * 32 + nt * 8 + g;
            bf[nt][0] = __float_as_uint(Bs[(kb + t4) * SB + n]);
            bf[nt][1] = __float_as_uint(Bs[(kb + t4 + 4) * SB + n]);
        }
        #pragma unroll
        for (int mt = 0; mt < 4; mt++)
            #pragma unroll
            for (int nt = 0; nt < 4; nt++)
                mma_tf32(acc[mt * 4 + nt],
                         af[mt][0], af[mt][1], af[mt][2], af[mt][3],
                         bf[nt][0], bf[nt][1]);
    }
}

// ---------------------------------------------------------------------------
// Prep: round to tf32 grid AND permute K dim in 16-groups.
// out[row][16g + 4a + b] = round(src[row][16g + 4b + a])
// ---------------------------------------------------------------------------
__global__ __launch_bounds__(256)
void k_round_perm(const float* __restrict__ src, float* __restrict__ dst,
                  int rows, int cols)
{
    int total4 = rows * (cols >> 2);
    int i = blockIdx.x * 256 + threadIdx.x;
    int stride = gridDim.x * 256;
    for (; i < total4; i += stride) {
        int row = i / (cols >> 2);
        int c4 = i % (cols >> 2);
        int base = (c4 >> 2) << 4;        // 16-group base col
        int a = c4 & 3;                   // which float4 within the group
        const float* s = src + (size_t)row * cols + base;
        float4 v;
        v.x = f2tf32f(s[0 + a]);
        v.y = f2tf32f(s[4 + a]);
        v.z = f2tf32f(s[8 + a]);
        v.w = f2tf32f(s[12 + a]);
        *(float4*)(dst + (size_t)row * cols + base + 4 * a) = v;
    }
}

// W (CDIM x N3) -> W^T (N3 x CDIM), rounded, K(=CDIM) permuted in 16-groups.
__global__ __launch_bounds__(256)
void k_transpose_round_perm(const float* __restrict__ src, float* __restrict__ dst)
{
    __shared__ float t[32][33];
    const int bx = blockIdx.x * 32;   // over N3 (n)
    const int by = blockIdx.y * 32;   // over CDIM (k)
    const int tx = threadIdx.x & 31;
    const int ty = threadIdx.x >> 5;  // 0..7
    #pragma unroll
    for (int i = 0; i < 32; i += 8)
        t[ty + i][tx] = src[(size_t)(by + ty + i) * N3 + bx + tx];
    __syncthreads();
    // out col (k) = by + tx, permuted within its 16-group
    const int kpos = by + (tx & 16) + 4 * (tx & 3) + ((tx & 15) >> 2);
    #pragma unroll
    for (int i = 0; i < 32; i += 8)
        dst[(size_t)(bx + ty + i) * CDIM + kpos] = f2tf32f(t[tx][ty + i]);
}

// ---------------------------------------------------------------------------
// Kernel 1: qkv = x @ W + b  (NT: A=g_xr rows, B=g_wt rows, both K-permuted).
// Q/K feature columns written PERMUTED into g_qkv; V columns original.
// ---------------------------------------------------------------------------
__global__ __launch_bounds__(256, 2)
void k_gemm_qkv(const float* __restrict__ bias)
{
    extern __shared__ float sm[];
    float* As[2] = { sm,               sm + BM * SA };
    float* Bs[2] = { sm + 2 * BM * SA, sm + 3 * BM * SA };

    const int tid = threadIdx.x;
    const int lane = tid & 31, wid = tid >> 5;
    const int wm = wid & 1, wn = wid >> 1;
    const int g = lane >> 2, t4 = lane & 3;
    const int m0 = blockIdx.y * BM;
    const int n0 = blockIdx.x * BN;

    float acc[16][4];
    #pragma unroll
    for (int i = 0; i < 16; i++)
        #pragma unroll
        for (int j = 0; j < 4; j++) acc[i][j] = 0.f;

    const int nk = CDIM / BK;
    loadA_async(As[0], g_xr + (size_t)m0 * CDIM, CDIM, tid);
    loadA_async(Bs[0], g_wt + (size_t)n0 * CDIM, CDIM, tid);
    CP_COMMIT();

    int buf = 0;
    for (int it = 0; it < nk; it++) {
        CP_WAIT0();
        __syncthreads();
        if (it + 1 < nk) {
            const int kn = (it + 1) * BK;
            loadA_async(As[buf ^ 1], g_xr + (size_t)m0 * CDIM + kn, CDIM, tid);
            loadA_async(Bs[buf ^ 1], g_wt + (size_t)n0 * CDIM + kn, CDIM, tid);
            CP_COMMIT();
        }
        compute_NT_vec(As[buf], Bs[buf], acc, wm, wn, g, t4);
        buf ^= 1;
    }

    const bool isV = (n0 >= 2 * NF);
    #pragma unroll
    for (int mt = 0; mt < 4; mt++) {
        const int row = m0 + wm * 64 + mt * 16 + g;
        #pragma unroll
        for (int nt = 0; nt < 4; nt++) {
            #pragma unroll
            for (int e = 0; e < 2; e++) {
                const int f = n0 + wn * 32 + nt * 8 + t4 * 2 + e;
                const float bv = bias[f];
                const int col = isV ? f : perm16(f);
                g_qkv[(size_t)row * N3 + col]       = f2tf32f(acc[mt*4+nt][e]     + bv);
                g_qkv[(size_t)(row + 8) * N3 + col] = f2tf32f(acc[mt*4+nt][2 + e] + bv);
            }
        }
    }
}

// ---------------------------------------------------------------------------
// Kernel 2: S = scale * Q @ K^T (NT, feature dim permuted on both sides).
// S written in ORIGINAL column order.
// ---------------------------------------------------------------------------
__global__ __launch_bounds__(256, 2)
void k_gemm_s(const int* __restrict__ n_padd_p)
{
    const int np = *n_padd_p;
    const int rm = blockIdx.y * BM;
    const int cn = blockIdx.x * BN;
    if (cn >= rm + BM) return;
    if (cn + BN <= np) return;
    if (rm + BM <= np) return;

    extern __shared__ float sm[];
    float* As[2] = { sm,               sm + BM * SA };
    float* Ks[2] = { sm + 2 * BM * SA, sm + 3 * BM * SA };

    const int tid = threadIdx.x;
    const int lane = tid & 31, wid = tid >> 5;
    const int wm = wid & 1, wn = wid >> 1;
    const int g = lane >> 2, t4 = lane & 3;

    float acc[16][4];
    #pragma unroll
    for (int i = 0; i < 16; i++)
        #pragma unroll
        for (int j = 0; j < 4; j++) acc[i][j] = 0.f;

    const int nk = NF / BK;
    loadA_async(As[0], g_qkv + (size_t)rm * N3, N3, tid);
    loadA_async(Ks[0], g_qkv + (size_t)cn * N3 + NF, N3, tid);
    CP_COMMIT();

    int buf = 0;
    for (int it = 0; it < nk; it++) {
        CP_WAIT0();
        __syncthreads();
        if (it + 1 < nk) {
            const int kn = (it + 1) * BK;
            loadA_async(As[buf ^ 1], g_qkv + (size_t)rm * N3 + kn, N3, tid);
            loadA_async(Ks[buf ^ 1], g_qkv + (size_t)cn * N3 + NF + kn, N3, tid);
            CP_COMMIT();
        }
        compute_NT_vec(As[buf], Ks[buf], acc, wm, wn, g, t4);
        buf ^= 1;
    }

    const float scale = rsqrtf((float)NF);
    #pragma unroll
    for (int mt = 0; mt < 4; mt++) {
        #pragma unroll
        for (int nt = 0; nt < 4; nt++) {
            const int row = rm + wm * 64 + mt * 16 + g;
            const int col = cn + wn * 32 + nt * 8 + t4 * 2;
            *(float2*)(g_P + (size_t)row * TDIM + col) =
                make_float2(acc[mt*4+nt][0] * scale, acc[mt*4+nt][1] * scale);
            *(float2*)(g_P + (size_t)(row + 8) * TDIM + col) =
                make_float2(acc[mt*4+nt][2] * scale, acc[mt*4+nt][3] * scale);
        }
    }
}

// ---------------------------------------------------------------------------
// Kernel 3: row softmax in-place on g_P; writes tf32-rounded probabilities.
// ---------------------------------------------------------------------------
__global__ __launch_bounds__(256)
void k_softmax(const int* __restrict__ n_padd_p)
{
    const int r = blockIdx.x;
    const int np = *n_padd_p;
    const int tid = threadIdx.x;
    __shared__ float red[256];

    float* prow = g_P + (size_t)r * TDIM;

    if (r < np) {
        float4 z = make_float4(0.f, 0.f, 0.f, 0.f);
        for (int i = tid; i < TDIM / 4; i += 256)
            ((float4*)prow)[i] = z;
        return;
    }

    float m = -3.402823466e+38f;
    for (int c = np + tid; c <= r; c += 256) m = fmaxf(m, prow[c]);
    red[tid] = m; __syncthreads();
    for (int s = 128; s > 0; s >>= 1) {
        if (tid < s) red[tid] = fmaxf(red[tid], red[tid + s]);
        __syncthreads();
    }
    m = red[0];
    __syncthreads();

    for (int c = tid; c < np; c += 256) prow[c] = 0.f;
    for (int c = r + 1 + tid; c < TDIM; c += 256) prow[c] = 0.f;
    float sum = 0.f;
    for (int c = np + tid; c <= r; c += 256) {
        float e = __expf(prow[c] - m);
        prow[c] = e;
        sum += e;
    }
    red[tid] = sum; __syncthreads();
    for (int s = 128; s > 0; s >>= 1) {
        if (tid < s) red[tid] += red[tid + s];
        __syncthreads();
    }
    const float inv = 1.0f / red[0];

    for (int c = np + tid; c <= r; c += 256) prow[c] = f2tf32f(prow[c] * inv);
}

// ---------------------------------------------------------------------------
// Kernel 4: y = P @ V  (NN, original order), K-range clipped, 2-stage pipeline
// ---------------------------------------------------------------------------
__global__ __launch_bounds__(256, 2)
void k_gemm_pv(const int* __restrict__ n_padd_p, float* __restrict__ C)
{
    const int np = *n_padd_p;
    const int rm = blockIdx.y * BM;
    const int cn = blockIdx.x * BN;

    const int kstart = np & ~(BK - 1);
    const int kend   = rm + BM;
    const int nk = (kend > kstart) ? (kend - kstart) / BK : 0;

    extern __shared__ float sm[];
    float* As[2] = { sm,               sm + BM * SA };
    float* Bs[2] = { sm + 2 * BM * SA, sm + 2 * BM * SA + BK * SB };

    const int tid = threadIdx.x;
    const int lane = tid & 31, wid = tid >> 5;
    const int wm = wid & 1, wn = wid >> 1;
    const int g = lane >> 2, t4 = lane & 3;

    float acc[16][4];
    #pragma unroll
    for (int i = 0; i < 16; i++)
        #pragma unroll
        for (int j = 0; j < 4; j++) acc[i][j] = 0.f;

    if (nk > 0) {
        loadA_async(As[0], g_P + (size_t)rm * TDIM + kstart, TDIM, tid);
        loadB_async(Bs[0], g_qkv + (size_t)kstart * N3 + 2 * NF + cn, N3, tid);
        CP_COMMIT();
    }

    int buf = 0;
    for (int it = 0; it < nk; it++) {
        CP_WAIT0();
        __syncthreads();
        if (it + 1 < nk) {
            const int kn = kstart + (it + 1) * BK;
            loadA_async(As[buf ^ 1], g_P + (size_t)rm * TDIM + kn, TDIM, tid);
            loadB_async(Bs[buf ^ 1], g_qkv + (size_t)kn * N3 + 2 * NF + cn, N3, tid);
            CP_COMMIT();
        }
        compute_NN(As[buf], Bs[buf], acc, wm, wn, g, t4);
        buf ^= 1;
    }

    #pragma unroll
    for (int mt = 0; mt < 4; mt++) {
        #pragma unroll
        for (int nt = 0; nt < 4; nt++) {
            const int row = rm + wm * 64 + mt * 16 + g;
            const int col = cn + wn * 32 + nt * 8 + t4 * 2;
            *(float2*)(C + (size_t)row * NF + col) =
                make_float2(acc[mt*4+nt][0], acc[mt*4+nt][1]);
            *(float2*)(C + (size_t)(row + 8) * NF + col) =
                make_float2(acc[mt*4+nt][2], acc[mt*4+nt][3]);
        }
    }
}

// ---------------------------------------------------------------------------
extern "C" void kernel_launch(void* const* d_in, const int* in_sizes, int n_in,
                              void* d_out, int out_size)
{
    const float* x  = (const float*)d_in[0];
    const float* W  = (const float*)d_in[1];
    const float* b  = (const float*)d_in[2];
    const int*   np = (const int*)d_in[3];
    float* y = (float*)d_out;
    (void)in_sizes; (void)n_in; (void)out_size;

    const int smem_nt = 4 * (BM * SA) * (int)sizeof(float);            // 73728
    const int smem_nn = 2 * (BM * SA + BK * SB) * (int)sizeof(float);  // 71680

    cudaFuncSetAttribute(k_gemm_qkv, cudaFuncAttributeMaxDynamicSharedMemorySize, smem_nt);
    cudaFuncSetAttribute(k_gemm_s,   cudaFuncAttributeMaxDynamicSharedMemorySize, smem_nt);
    cudaFuncSetAttribute(k_gemm_pv,  cudaFuncAttributeMaxDynamicSharedMemorySize, smem_nn);

    float* xr; float* wt;
    cudaGetSymbolAddress((void**)&xr, g_xr);
    cudaGetSymbolAddress((void**)&wt, g_wt);

    dim3 t(256);
    k_round_perm<<<1024, t>>>(x, xr, TDIM, CDIM);
    k_transpose_round_perm<<<dim3(N3 / 32, CDIM / 32), t>>>(W, wt);
    k_gemm_qkv<<<dim3(N3 / BN, TDIM / BM), t, smem_nt>>>(b);
    k_gemm_s<<<dim3(TDIM / BN, TDIM / BM), t, smem_nt>>>(np);
    k_softmax<<<TDIM, t>>>(np);
    k_gemm_pv<<<dim3(NF / BN, TDIM / BM), t, smem_nn>>>(np, y);
}

// round 10
// speedup vs baseline: 1.2668x; 1.2668x over previous
#include <cuda_runtime.h>
#include <cstdint>
#include <math.h>

// Problem dims (fixed by the reference)
#define TDIM 4096
#define CDIM 2048
#define NF   2048
#define N3   6144   // 3*NF

#define BM 128
#define BN 128
#define BK 32
#define SA 36    // padded A-tile stride (PV kernel, scalar path)
#define SB 136   // padded B NN tile stride (PV kernel)
#define SW 32    // unpadded swizzled tile stride (qkv/S kernels)

// Scratch (fp32, pre-rounded to tf32 grid).
// g_xr / g_wt: K dim permuted in 16-groups (j -> 4*(j%4)+j/4, an involution).
// g_qkv: Q and K feature columns permuted the same way; V columns original.
__device__ __align__(256) float g_qkv[(size_t)TDIM * N3];
__device__ __align__(256) float g_P[(size_t)TDIM * TDIM];
__device__ __align__(256) float g_xr[(size_t)TDIM * CDIM];
__device__ __align__(256) float g_wt[(size_t)N3 * CDIM];    // W^T [n][k], k permuted

__device__ __forceinline__ float f2tf32f(float x) {
    uint32_t u;
    asm("cvt.rna.tf32.f32 %0, %1;" : "=r"(u) : "f"(x));
    return __uint_as_float(u);
}

__device__ __forceinline__ void mma_tf32(float* d,
    uint32_t a0, uint32_t a1, uint32_t a2, uint32_t a3,
    uint32_t b0, uint32_t b1)
{
    asm volatile(
        "mma.sync.aligned.m16n8k8.row.col.f32.tf32.tf32.f32 "
        "{%0,%1,%2,%3}, {%4,%5,%6,%7}, {%8,%9}, {%0,%1,%2,%3};\n"
        : "+f"(d[0]), "+f"(d[1]), "+f"(d[2]), "+f"(d[3])
        : "r"(a0), "r"(a1), "r"(a2), "r"(a3), "r"(b0), "r"(b1));
}

__device__ __forceinline__ void cp16(float* smem_dst, const float* gsrc) {
    uint32_t s = (uint32_t)__cvta_generic_to_shared(smem_dst);
    asm volatile("cp.async.cg.shared.global [%0], [%1], 16;\n" :: "r"(s), "l"(gsrc));
}
#define CP_COMMIT() asm volatile("cp.async.commit_group;\n")
#define CP_WAIT0()  asm volatile("cp.async.wait_group 0;\n")

// permuted position of absolute column/index f (16-group involution)
__device__ __forceinline__ int perm16(int f) {
    int j = f & 15;
    return (f & ~15) + 4 * (j & 3) + (j >> 2);
}

// ---------------------------------------------------------------------------
// Swizzled tile helpers (qkv / S kernels).
// Tile: 128 rows x 32 floats, stride 32. float4 slot k4 of row r stored at
// slot (k4 ^ ((r&1)<<2)). Even rows occupy banks 0-15, odd rows banks 16-31
// within each LDS.128 phase -> conflict-free.
// ---------------------------------------------------------------------------
__device__ __forceinline__ void loadA_async_sw(float* tile, const float* __restrict__ src,
                                               size_t ld, int tid)
{
    #pragma unroll
    for (int i = 0; i < 4; i++) {
        int idx = tid + i * 256;
        int r = idx >> 3;
        int k4 = idx & 7;
        int sw = k4 ^ ((r & 1) << 2);
        cp16(tile + r * SW + sw * 4, src + (size_t)r * ld + k4 * 4);
    }
}

// Vectorized NT compute on swizzled tiles; K pre-permuted in 16-groups.
// One LDS.128 per row feeds TWO k8 MMA steps.
__device__ __forceinline__ void compute_NT_sw(const float* As, const float* Bs,
                                              float (*acc)[4], int wm, int wn, int g, int t4)
{
    const int x4 = (g & 1) << 2;   // row-parity XOR (rows m, m+8, n share parity g&1)
    #pragma unroll
    for (int q = 0; q < 2; q++) {
        const int koff = ((q * 4 + t4) ^ x4) * 4;
        float4 bv[4];
        #pragma unroll
        for (int nt = 0; nt < 4; nt++) {
            const int n = wn * 32 + nt * 8 + g;
            bv[nt] = *(const float4*)&Bs[n * SW + koff];
        }
        #pragma unroll
        for (int mt = 0; mt < 4; mt++) {
            const int m = wm * 64 + mt * 16 + g;
            float4 a0 = *(const float4*)&As[m * SW + koff];
            float4 a1 = *(const float4*)&As[(m + 8) * SW + koff];
            #pragma unroll
            for (int nt = 0; nt < 4; nt++)
                mma_tf32(acc[mt * 4 + nt],
                         __float_as_uint(a0.x), __float_as_uint(a1.x),
                         __float_as_uint(a0.y), __float_as_uint(a1.y),
                         __float_as_uint(bv[nt].x), __float_as_uint(bv[nt].y));
            #pragma unroll
            for (int nt = 0; nt < 4; nt++)
                mma_tf32(acc[mt * 4 + nt],
                         __float_as_uint(a0.z), __float_as_uint(a1.z),
                         __float_as_uint(a0.w), __float_as_uint(a1.w),
                         __float_as_uint(bv[nt].z), __float_as_uint(bv[nt].w));
        }
    }
}

// ---------------------------------------------------------------------------
// Round-4 scalar helpers (PV kernel): padded layouts, conflict-free.
// ---------------------------------------------------------------------------
__device__ __forceinline__ void loadA_async(float* tile, const float* __restrict__ src,
                                            size_t ld, int tid)
{
    #pragma unroll
    for (int i = 0; i < 4; i++) {
        int idx = tid + i * 256;
        int r = idx >> 3;
        int k = (idx & 7) << 2;
        cp16(tile + r * SA + k, src + (size_t)r * ld + k);
    }
}

__device__ __forceinline__ void loadB_async(float* tile, const float* __restrict__ src,
                                            size_t ld, int tid)
{
    #pragma unroll
    for (int i = 0; i < 4; i++) {
        int idx = tid + i * 256;
        int k = idx >> 5;
        int n = (idx & 31) << 2;
        cp16(tile + k * SB + n, src + (size_t)k * ld + n);
    }
}

__device__ __forceinline__ void compute_NN(const float* As, const float* Bs,
                                           float (*acc)[4], int wm, int wn, int g, int t4)
{
    #pragma unroll
    for (int ks = 0; ks < 4; ks++) {
        const int kb = ks * 8;
        uint32_t af[4][4], bf[4][2];
        #pragma unroll
        for (int mt = 0; mt < 4; mt++) {
            const int m = wm * 64 + mt * 16 + g;
            af[mt][0] = __float_as_uint(As[m * SA + kb + t4]);
            af[mt][1] = __float_as_uint(As[(m + 8) * SA + kb + t4]);
            af[mt][2] = __float_as_uint(As[m * SA + kb + t4 + 4]);
            af[mt][3] = __float_as_uint(As[(m + 8) * SA + kb + t4 + 4]);
        }
        #pragma unroll
        for (int nt = 0; nt < 4; nt++) {
            const int n = wn * 32 + nt * 8 + g;
            bf[nt][0] = __float_as_uint(Bs[(kb + t4) * SB + n]);
            bf[nt][1] = __float_as_uint(Bs[(kb + t4 + 4) * SB + n]);
        }
        #pragma unroll
        for (int mt = 0; mt < 4; mt++)
            #pragma unroll
            for (int nt = 0; nt < 4; nt++)
                mma_tf32(acc[mt * 4 + nt],
                         af[mt][0], af[mt][1], af[mt][2], af[mt][3],
                         bf[nt][0], bf[nt][1]);
    }
}

// ---------------------------------------------------------------------------
// Prep: round to tf32 grid AND permute K dim in 16-groups.
// ---------------------------------------------------------------------------
__global__ __launch_bounds__(256)
void k_round_perm(const float* __restrict__ src, float* __restrict__ dst,
                  int rows, int cols)
{
    int total4 = rows * (cols >> 2);
    int i = blockIdx.x * 256 + threadIdx.x;
    int stride = gridDim.x * 256;
    for (; i < total4; i += stride) {
        int row = i / (cols >> 2);
        int c4 = i % (cols >> 2);
        int base = (c4 >> 2) << 4;
        int a = c4 & 3;
        const float* s = src + (size_t)row * cols + base;
        float4 v;
        v.x = f2tf32f(s[0 + a]);
        v.y = f2tf32f(s[4 + a]);
        v.z = f2tf32f(s[8 + a]);
        v.w = f2tf32f(s[12 + a]);
        *(float4*)(dst + (size_t)row * cols + base + 4 * a) = v;
    }
}

// W (CDIM x N3) -> W^T (N3 x CDIM), rounded, K permuted in 16-groups.
__global__ __launch_bounds__(256)
void k_transpose_round_perm(const float* __restrict__ src, float* __restrict__ dst)
{
    __shared__ float t[32][33];
    const int bx = blockIdx.x * 32;
    const int by = blockIdx.y * 32;
    const int tx = threadIdx.x & 31;
    const int ty = threadIdx.x >> 5;
    #pragma unroll
    for (int i = 0; i < 32; i += 8)
        t[ty + i][tx] = src[(size_t)(by + ty + i) * N3 + bx + tx];
    __syncthreads();
    const int kpos = by + (tx & 16) + 4 * (tx & 3) + ((tx & 15) >> 2);
    #pragma unroll
    for (int i = 0; i < 32; i += 8)
        dst[(size_t)(bx + ty + i) * CDIM + kpos] = f2tf32f(t[tx][ty + i]);
}

// ---------------------------------------------------------------------------
// Kernel 1: qkv = x @ W + b  (NT, swizzled vectorized path).
// Q/K feature columns written PERMUTED into g_qkv; V columns original.
// ---------------------------------------------------------------------------
__global__ __launch_bounds__(256, 2)
void k_gemm_qkv(const float* __restrict__ bias)
{
    extern __shared__ float sm[];
    float* As[2] = { sm,               sm + BM * SW };
    float* Bs[2] = { sm + 2 * BM * SW, sm + 3 * BM * SW };

    const int tid = threadIdx.x;
    const int lane = tid & 31, wid = tid >> 5;
    const int wm = wid & 1, wn = wid >> 1;
    const int g = lane >> 2, t4 = lane & 3;
    const int m0 = blockIdx.y * BM;
    const int n0 = blockIdx.x * BN;

    float acc[16][4];
    #pragma unroll
    for (int i = 0; i < 16; i++)
        #pragma unroll
        for (int j = 0; j < 4; j++) acc[i][j] = 0.f;

    const int nk = CDIM / BK;
    loadA_async_sw(As[0], g_xr + (size_t)m0 * CDIM, CDIM, tid);
    loadA_async_sw(Bs[0], g_wt + (size_t)n0 * CDIM, CDIM, tid);
    CP_COMMIT();

    int buf = 0;
    for (int it = 0; it < nk; it++) {
        CP_WAIT0();
        __syncthreads();
        if (it + 1 < nk) {
            const int kn = (it + 1) * BK;
            loadA_async_sw(As[buf ^ 1], g_xr + (size_t)m0 * CDIM + kn, CDIM, tid);
            loadA_async_sw(Bs[buf ^ 1], g_wt + (size_t)n0 * CDIM + kn, CDIM, tid);
            CP_COMMIT();
        }
        compute_NT_sw(As[buf], Bs[buf], acc, wm, wn, g, t4);
        buf ^= 1;
    }

    const bool isV = (n0 >= 2 * NF);
    #pragma unroll
    for (int mt = 0; mt < 4; mt++) {
        const int row = m0 + wm * 64 + mt * 16 + g;
        #pragma unroll
        for (int nt = 0; nt < 4; nt++) {
            #pragma unroll
            for (int e = 0; e < 2; e++) {
                const int f = n0 + wn * 32 + nt * 8 + t4 * 2 + e;
                const float bv = bias[f];
                const int col = isV ? f : perm16(f);
                g_qkv[(size_t)row * N3 + col]       = f2tf32f(acc[mt*4+nt][e]     + bv);
                g_qkv[(size_t)(row + 8) * N3 + col] = f2tf32f(acc[mt*4+nt][2 + e] + bv);
            }
        }
    }
}

// ---------------------------------------------------------------------------
// Kernel 2: S = scale * Q @ K^T (NT, swizzled vectorized; feature dim permuted
// on both sides). S written in ORIGINAL column order.
// ---------------------------------------------------------------------------
__global__ __launch_bounds__(256, 2)
void k_gemm_s(const int* __restrict__ n_padd_p)
{
    const int np = *n_padd_p;
    const int rm = blockIdx.y * BM;
    const int cn = blockIdx.x * BN;
    if (cn >= rm + BM) return;
    if (cn + BN <= np) return;
    if (rm + BM <= np) return;

    extern __shared__ float sm[];
    float* As[2] = { sm,               sm + BM * SW };
    float* Ks[2] = { sm + 2 * BM * SW, sm + 3 * BM * SW };

    const int tid = threadIdx.x;
    const int lane = tid & 31, wid = tid >> 5;
    const int wm = wid & 1, wn = wid >> 1;
    const int g = lane >> 2, t4 = lane & 3;

    float acc[16][4];
    #pragma unroll
    for (int i = 0; i < 16; i++)
        #pragma unroll
        for (int j = 0; j < 4; j++) acc[i][j] = 0.f;

    const int nk = NF / BK;
    loadA_async_sw(As[0], g_qkv + (size_t)rm * N3, N3, tid);
    loadA_async_sw(Ks[0], g_qkv + (size_t)cn * N3 + NF, N3, tid);
    CP_COMMIT();

    int buf = 0;
    for (int it = 0; it < nk; it++) {
        CP_WAIT0();
        __syncthreads();
        if (it + 1 < nk) {
            const int kn = (it + 1) * BK;
            loadA_async_sw(As[buf ^ 1], g_qkv + (size_t)rm * N3 + kn, N3, tid);
            loadA_async_sw(Ks[buf ^ 1], g_qkv + (size_t)cn * N3 + NF + kn, N3, tid);
            CP_COMMIT();
        }
        compute_NT_sw(As[buf], Ks[buf], acc, wm, wn, g, t4);
        buf ^= 1;
    }

    const float scale = rsqrtf((float)NF);
    #pragma unroll
    for (int mt = 0; mt < 4; mt++) {
        #pragma unroll
        for (int nt = 0; nt < 4; nt++) {
            const int row = rm + wm * 64 + mt * 16 + g;
            const int col = cn + wn * 32 + nt * 8 + t4 * 2;
            *(float2*)(g_P + (size_t)row * TDIM + col) =
                make_float2(acc[mt*4+nt][0] * scale, acc[mt*4+nt][1] * scale);
            *(float2*)(g_P + (size_t)(row + 8) * TDIM + col) =
                make_float2(acc[mt*4+nt][2] * scale, acc[mt*4+nt][3] * scale);
        }
    }
}

// ---------------------------------------------------------------------------
// Kernel 3: row softmax in-place on g_P; writes tf32-rounded probabilities.
// ---------------------------------------------------------------------------
__global__ __launch_bounds__(256)
void k_softmax(const int* __restrict__ n_padd_p)
{
    const int r = blockIdx.x;
    const int np = *n_padd_p;
    const int tid = threadIdx.x;
    __shared__ float red[256];

    float* prow = g_P + (size_t)r * TDIM;

    if (r < np) {
        float4 z = make_float4(0.f, 0.f, 0.f, 0.f);
        for (int i = tid; i < TDIM / 4; i += 256)
            ((float4*)prow)[i] = z;
        return;
    }

    float m = -3.402823466e+38f;
    for (int c = np + tid; c <= r; c += 256) m = fmaxf(m, prow[c]);
    red[tid] = m; __syncthreads();
    for (int s = 128; s > 0; s >>= 1) {
        if (tid < s) red[tid] = fmaxf(red[tid], red[tid + s]);
        __syncthreads();
    }
    m = red[0];
    __syncthreads();

    for (int c = tid; c < np; c += 256) prow[c] = 0.f;
    for (int c = r + 1 + tid; c < TDIM; c += 256) prow[c] = 0.f;
    float sum = 0.f;
    for (int c = np + tid; c <= r; c += 256) {
        float e = __expf(prow[c] - m);
        prow[c] = e;
        sum += e;
    }
    red[tid] = sum; __syncthreads();
    for (int s = 128; s > 0; s >>= 1) {
        if (tid < s) red[tid] += red[tid + s];
        __syncthreads();
    }
    const float inv = 1.0f / red[0];

    for (int c = np + tid; c <= r; c += 256) prow[c] = f2tf32f(prow[c] * inv);
}

// ---------------------------------------------------------------------------
// Kernel 4: y = P @ V  (NN, round-4 scalar path), K-range clipped.
// ---------------------------------------------------------------------------
__global__ __launch_bounds__(256, 2)
void k_gemm_pv(const int* __restrict__ n_padd_p, float* __restrict__ C)
{
    const int np = *n_padd_p;
    const int rm = blockIdx.y * BM;
    const int cn = blockIdx.x * BN;

    const int kstart = np & ~(BK - 1);
    const int kend   = rm + BM;
    const int nk = (kend > kstart) ? (kend - kstart) / BK : 0;

    extern __shared__ float sm[];
    float* As[2] = { sm,               sm + BM * SA };
    float* Bs[2] = { sm + 2 * BM * SA, sm + 2 * BM * SA + BK * SB };

    const int tid = threadIdx.x;
    const int lane = tid & 31, wid = tid >> 5;
    const int wm = wid & 1, wn = wid >> 1;
    const int g = lane >> 2, t4 = lane & 3;

    float acc[16][4];
    #pragma unroll
    for (int i = 0; i < 16; i++)
        #pragma unroll
        for (int j = 0; j < 4; j++) acc[i][j] = 0.f;

    if (nk > 0) {
        loadA_async(As[0], g_P + (size_t)rm * TDIM + kstart, TDIM, tid);
        loadB_async(Bs[0], g_qkv + (size_t)kstart * N3 + 2 * NF + cn, N3, tid);
        CP_COMMIT();
    }

    int buf = 0;
    for (int it = 0; it < nk; it++) {
        CP_WAIT0();
        __syncthreads();
        if (it + 1 < nk) {
            const int kn = kstart + (it + 1) * BK;
            loadA_async(As[buf ^ 1], g_P + (size_t)rm * TDIM + kn, TDIM, tid);
            loadB_async(Bs[buf ^ 1], g_qkv + (size_t)kn * N3 + 2 * NF + cn, N3, tid);
            CP_COMMIT();
        }
        compute_NN(As[buf], Bs[buf], acc, wm, wn, g, t4);
        buf ^= 1;
    }

    #pragma unroll
    for (int mt = 0; mt < 4; mt++) {
        #pragma unroll
        for (int nt = 0; nt < 4; nt++) {
            const int row = rm + wm * 64 + mt * 16 + g;
            const int col = cn + wn * 32 + nt * 8 + t4 * 2;
            *(float2*)(C + (size_t)row * NF + col) =
                make_float2(acc[mt*4+nt][0], acc[mt*4+nt][1]);
            *(float2*)(C + (size_t)(row + 8) * NF + col) =
                make_float2(acc[mt*4+nt][2], acc[mt*4+nt][3]);
        }
    }
}

// ---------------------------------------------------------------------------
extern "C" void kernel_launch(void* const* d_in, const int* in_sizes, int n_in,
                              void* d_out, int out_size)
{
    const float* x  = (const float*)d_in[0];
    const float* W  = (const float*)d_in[1];
    const float* b  = (const float*)d_in[2];
    const int*   np = (const int*)d_in[3];
    float* y = (float*)d_out;
    (void)in_sizes; (void)n_in; (void)out_size;

    const int smem_sw = 4 * (BM * SW) * (int)sizeof(float);            // 65536
    const int smem_nn = 2 * (BM * SA + BK * SB) * (int)sizeof(float);  // 71680

    cudaFuncSetAttribute(k_gemm_qkv, cudaFuncAttributeMaxDynamicSharedMemorySize, smem_sw);
    cudaFuncSetAttribute(k_gemm_s,   cudaFuncAttributeMaxDynamicSharedMemorySize, smem_sw);
    cudaFuncSetAttribute(k_gemm_pv,  cudaFuncAttributeMaxDynamicSharedMemorySize, smem_nn);

    float* xr; float* wt;
    cudaGetSymbolAddress((void**)&xr, g_xr);
    cudaGetSymbolAddress((void**)&wt, g_wt);

    dim3 t(256);
    k_round_perm<<<1024, t>>>(x, xr, TDIM, CDIM);
    k_transpose_round_perm<<<dim3(N3 / 32, CDIM / 32), t>>>(W, wt);
    k_gemm_qkv<<<dim3(N3 / BN, TDIM / BM), t, smem_sw>>>(b);
    k_gemm_s<<<dim3(TDIM / BN, TDIM / BM), t, smem_sw>>>(np);
    k_softmax<<<TDIM, t>>>(np);
    k_gemm_pv<<<dim3(NF / BN, TDIM / BM), t, smem_nn>>>(np, y);
}

// round 11
// speedup vs baseline: 1.3074x; 1.0321x over previous
#include <cuda_runtime.h>
#include <cstdint>
#include <math.h>

// Problem dims (fixed by the reference)
#define TDIM 4096
#define CDIM 2048
#define NF   2048
#define N3   6144   // 3*NF

#define BM 128
#define BN 128
#define BK 32
#define SW 32    // unpadded swizzled tile stride (all GEMMs)

// Scratch (fp32, pre-rounded to tf32 grid).
// g_xr / g_wt: K dim permuted in 16-groups (j -> 4*(j%4)+j/4, an involution).
// g_qkv: Q and K feature columns permuted; V columns original.
// g_vt:  V^T [n][t] with t permuted in 16-groups.
// g_P:   post-softmax probabilities with column (t) dim permuted in 16-groups.
__device__ __align__(256) float g_qkv[(size_t)TDIM * N3];
__device__ __align__(256) float g_P[(size_t)TDIM * TDIM];
__device__ __align__(256) float g_vt[(size_t)NF * TDIM];
__device__ __align__(256) float g_xr[(size_t)TDIM * CDIM];
__device__ __align__(256) float g_wt[(size_t)N3 * CDIM];    // W^T [n][k], k permuted

__device__ __forceinline__ float f2tf32f(float x) {
    uint32_t u;
    asm("cvt.rna.tf32.f32 %0, %1;" : "=r"(u) : "f"(x));
    return __uint_as_float(u);
}

__device__ __forceinline__ void mma_tf32(float* d,
    uint32_t a0, uint32_t a1, uint32_t a2, uint32_t a3,
    uint32_t b0, uint32_t b1)
{
    asm volatile(
        "mma.sync.aligned.m16n8k8.row.col.f32.tf32.tf32.f32 "
        "{%0,%1,%2,%3}, {%4,%5,%6,%7}, {%8,%9}, {%0,%1,%2,%3};\n"
        : "+f"(d[0]), "+f"(d[1]), "+f"(d[2]), "+f"(d[3])
        : "r"(a0), "r"(a1), "r"(a2), "r"(a3), "r"(b0), "r"(b1));
}

__device__ __forceinline__ void cp16(float* smem_dst, const float* gsrc) {
    uint32_t s = (uint32_t)__cvta_generic_to_shared(smem_dst);
    asm volatile("cp.async.cg.shared.global [%0], [%1], 16;\n" :: "r"(s), "l"(gsrc));
}
#define CP_COMMIT() asm volatile("cp.async.commit_group;\n")
#define CP_WAIT0()  asm volatile("cp.async.wait_group 0;\n")

// permuted position of absolute index f (16-group involution)
__device__ __forceinline__ int perm16(int f) {
    int j = f & 15;
    return (f & ~15) + 4 * (j & 3) + (j >> 2);
}

// ---------------------------------------------------------------------------
// Swizzled tile helpers: 128 rows x 32 floats, stride 32. float4 slot k4 of
// row r stored at slot (k4 ^ ((r&1)<<2)) -> LDS.128 conflict-free.
// ---------------------------------------------------------------------------
__device__ __forceinline__ void loadA_async_sw(float* tile, const float* __restrict__ src,
                                               size_t ld, int tid)
{
    #pragma unroll
    for (int i = 0; i < 4; i++) {
        int idx = tid + i * 256;
        int r = idx >> 3;
        int k4 = idx & 7;
        int sw = k4 ^ ((r & 1) << 2);
        cp16(tile + r * SW + sw * 4, src + (size_t)r * ld + k4 * 4);
    }
}

// Vectorized NT compute on swizzled tiles; K pre-permuted in 16-groups.
__device__ __forceinline__ void compute_NT_sw(const float* As, const float* Bs,
                                              float (*acc)[4], int wm, int wn, int g, int t4)
{
    const int x4 = (g & 1) << 2;
    #pragma unroll
    for (int q = 0; q < 2; q++) {
        const int koff = ((q * 4 + t4) ^ x4) * 4;
        float4 bv[4];
        #pragma unroll
        for (int nt = 0; nt < 4; nt++) {
            const int n = wn * 32 + nt * 8 + g;
            bv[nt] = *(const float4*)&Bs[n * SW + koff];
        }
        #pragma unroll
        for (int mt = 0; mt < 4; mt++) {
            const int m = wm * 64 + mt * 16 + g;
            float4 a0 = *(const float4*)&As[m * SW + koff];
            float4 a1 = *(const float4*)&As[(m + 8) * SW + koff];
            #pragma unroll
            for (int nt = 0; nt < 4; nt++)
                mma_tf32(acc[mt * 4 + nt],
                         __float_as_uint(a0.x), __float_as_uint(a1.x),
                         __float_as_uint(a0.y), __float_as_uint(a1.y),
                         __float_as_uint(bv[nt].x), __float_as_uint(bv[nt].y));
            #pragma unroll
            for (int nt = 0; nt < 4; nt++)
                mma_tf32(acc[mt * 4 + nt],
                         __float_as_uint(a0.z), __float_as_uint(a1.z),
                         __float_as_uint(a0.w), __float_as_uint(a1.w),
                         __float_as_uint(bv[nt].z), __float_as_uint(bv[nt].w));
        }
    }
}

// ---------------------------------------------------------------------------
// Prep: round to tf32 grid AND permute K dim in 16-groups.
// ---------------------------------------------------------------------------
__global__ __launch_bounds__(256)
void k_round_perm(const float* __restrict__ src, float* __restrict__ dst,
                  int rows, int cols)
{
    int total4 = rows * (cols >> 2);
    int i = blockIdx.x * 256 + threadIdx.x;
    int stride = gridDim.x * 256;
    for (; i < total4; i += stride) {
        int row = i / (cols >> 2);
        int c4 = i % (cols >> 2);
        int base = (c4 >> 2) << 4;
        int a = c4 & 3;
        const float* s = src + (size_t)row * cols + base;
        float4 v;
        v.x = f2tf32f(s[0 + a]);
        v.y = f2tf32f(s[4 + a]);
        v.z = f2tf32f(s[8 + a]);
        v.w = f2tf32f(s[12 + a]);
        *(float4*)(dst + (size_t)row * cols + base + 4 * a) = v;
    }
}

// W (CDIM x N3) -> W^T (N3 x CDIM), rounded, K permuted in 16-groups.
__global__ __launch_bounds__(256)
void k_transpose_round_perm(const float* __restrict__ src, float* __restrict__ dst)
{
    __shared__ float t[32][33];
    const int bx = blockIdx.x * 32;
    const int by = blockIdx.y * 32;
    const int tx = threadIdx.x & 31;
    const int ty = threadIdx.x >> 5;
    #pragma unroll
    for (int i = 0; i < 32; i += 8)
        t[ty + i][tx] = src[(size_t)(by + ty + i) * N3 + bx + tx];
    __syncthreads();
    const int kpos = by + (tx & 16) + 4 * (tx & 3) + ((tx & 15) >> 2);
    #pragma unroll
    for (int i = 0; i < 32; i += 8)
        dst[(size_t)(bx + ty + i) * CDIM + kpos] = f2tf32f(t[tx][ty + i]);
}

// V slice of g_qkv (t x n, already rounded) -> g_vt[n][perm16(t)]
__global__ __launch_bounds__(256)
void k_transpose_v()
{
    __shared__ float t[32][33];
    const int bx = blockIdx.x * 32;   // over n (NF)
    const int by = blockIdx.y * 32;   // over t (TDIM)
    const int tx = threadIdx.x & 31;
    const int ty = threadIdx.x >> 5;
    #pragma unroll
    for (int i = 0; i < 32; i += 8)
        t[ty + i][tx] = g_qkv[(size_t)(by + ty + i) * N3 + 2 * NF + bx + tx];
    __syncthreads();
    const int kpos = by + (tx & 16) + 4 * (tx & 3) + ((tx & 15) >> 2);
    #pragma unroll
    for (int i = 0; i < 32; i += 8)
        g_vt[(size_t)(bx + ty + i) * TDIM + kpos] = t[tx][ty + i];
}

// ---------------------------------------------------------------------------
// Kernel 1: qkv = x @ W + b  (NT, swizzled vectorized path).
// Q/K feature columns written PERMUTED into g_qkv; V columns original.
// ---------------------------------------------------------------------------
__global__ __launch_bounds__(256, 2)
void k_gemm_qkv(const float* __restrict__ bias)
{
    extern __shared__ float sm[];
    float* As[2] = { sm,               sm + BM * SW };
    float* Bs[2] = { sm + 2 * BM * SW, sm + 3 * BM * SW };

    const int tid = threadIdx.x;
    const int lane = tid & 31, wid = tid >> 5;
    const int wm = wid & 1, wn = wid >> 1;
    const int g = lane >> 2, t4 = lane & 3;
    const int m0 = blockIdx.y * BM;
    const int n0 = blockIdx.x * BN;

    float acc[16][4];
    #pragma unroll
    for (int i = 0; i < 16; i++)
        #pragma unroll
        for (int j = 0; j < 4; j++) acc[i][j] = 0.f;

    const int nk = CDIM / BK;
    loadA_async_sw(As[0], g_xr + (size_t)m0 * CDIM, CDIM, tid);
    loadA_async_sw(Bs[0], g_wt + (size_t)n0 * CDIM, CDIM, tid);
    CP_COMMIT();

    int buf = 0;
    for (int it = 0; it < nk; it++) {
        CP_WAIT0();
        __syncthreads();
        if (it + 1 < nk) {
            const int kn = (it + 1) * BK;
            loadA_async_sw(As[buf ^ 1], g_xr + (size_t)m0 * CDIM + kn, CDIM, tid);
            loadA_async_sw(Bs[buf ^ 1], g_wt + (size_t)n0 * CDIM + kn, CDIM, tid);
            CP_COMMIT();
        }
        compute_NT_sw(As[buf], Bs[buf], acc, wm, wn, g, t4);
        buf ^= 1;
    }

    const bool isV = (n0 >= 2 * NF);
    #pragma unroll
    for (int mt = 0; mt < 4; mt++) {
        const int row = m0 + wm * 64 + mt * 16 + g;
        #pragma unroll
        for (int nt = 0; nt < 4; nt++) {
            #pragma unroll
            for (int e = 0; e < 2; e++) {
                const int f = n0 + wn * 32 + nt * 8 + t4 * 2 + e;
                const float bv = bias[f];
                const int col = isV ? f : perm16(f);
                g_qkv[(size_t)row * N3 + col]       = f2tf32f(acc[mt*4+nt][e]     + bv);
                g_qkv[(size_t)(row + 8) * N3 + col] = f2tf32f(acc[mt*4+nt][2 + e] + bv);
            }
        }
    }
}

// ---------------------------------------------------------------------------
// Kernel 2: S = scale * Q @ K^T (NT, swizzled vectorized; feature dim permuted
// on both sides). S written in ORIGINAL column order.
// ---------------------------------------------------------------------------
__global__ __launch_bounds__(256, 2)
void k_gemm_s(const int* __restrict__ n_padd_p)
{
    const int np = *n_padd_p;
    const int rm = blockIdx.y * BM;
    const int cn = blockIdx.x * BN;
    if (cn >= rm + BM) return;
    if (cn + BN <= np) return;
    if (rm + BM <= np) return;

    extern __shared__ float sm[];
    float* As[2] = { sm,               sm + BM * SW };
    float* Ks[2] = { sm + 2 * BM * SW, sm + 3 * BM * SW };

    const int tid = threadIdx.x;
    const int lane = tid & 31, wid = tid >> 5;
    const int wm = wid & 1, wn = wid >> 1;
    const int g = lane >> 2, t4 = lane & 3;

    float acc[16][4];
    #pragma unroll
    for (int i = 0; i < 16; i++)
        #pragma unroll
        for (int j = 0; j < 4; j++) acc[i][j] = 0.f;

    const int nk = NF / BK;
    loadA_async_sw(As[0], g_qkv + (size_t)rm * N3, N3, tid);
    loadA_async_sw(Ks[0], g_qkv + (size_t)cn * N3 + NF, N3, tid);
    CP_COMMIT();

    int buf = 0;
    for (int it = 0; it < nk; it++) {
        CP_WAIT0();
        __syncthreads();
        if (it + 1 < nk) {
            const int kn = (it + 1) * BK;
            loadA_async_sw(As[buf ^ 1], g_qkv + (size_t)rm * N3 + kn, N3, tid);
            loadA_async_sw(Ks[buf ^ 1], g_qkv + (size_t)cn * N3 + NF + kn, N3, tid);
            CP_COMMIT();
        }
        compute_NT_sw(As[buf], Ks[buf], acc, wm, wn, g, t4);
        buf ^= 1;
    }

    const float scale = rsqrtf((float)NF);
    #pragma unroll
    for (int mt = 0; mt < 4; mt++) {
        #pragma unroll
        for (int nt = 0; nt < 4; nt++) {
            const int row = rm + wm * 64 + mt * 16 + g;
            const int col = cn + wn * 32 + nt * 8 + t4 * 2;
            *(float2*)(g_P + (size_t)row * TDIM + col) =
                make_float2(acc[mt*4+nt][0] * scale, acc[mt*4+nt][1] * scale);
            *(float2*)(g_P + (size_t)(row + 8) * TDIM + col) =
                make_float2(acc[mt*4+nt][2] * scale, acc[mt*4+nt][3] * scale);
        }
    }
}

// ---------------------------------------------------------------------------
// Kernel 3: row softmax in-place on g_P. Final pass writes tf32-rounded
// probabilities PERMUTED within 16-column groups (thread owns one group).
// ---------------------------------------------------------------------------
__global__ __launch_bounds__(256)
void k_softmax(const int* __restrict__ n_padd_p)
{
    const int r = blockIdx.x;
    const int np = *n_padd_p;
    const int tid = threadIdx.x;
    __shared__ float red[256];

    float* prow = g_P + (size_t)r * TDIM;

    if (r < np) {
        float4 z = make_float4(0.f, 0.f, 0.f, 0.f);
        for (int i = tid; i < TDIM / 4; i += 256)
            ((float4*)prow)[i] = z;
        return;
    }

    float m = -3.402823466e+38f;
    for (int c = np + tid; c <= r; c += 256) m = fmaxf(m, prow[c]);
    red[tid] = m; __syncthreads();
    for (int s = 128; s > 0; s >>= 1) {
        if (tid < s) red[tid] = fmaxf(red[tid], red[tid + s]);
        __syncthreads();
    }
    m = red[0];
    __syncthreads();

    for (int c = tid; c < np; c += 256) prow[c] = 0.f;
    for (int c = r + 1 + tid; c < TDIM; c += 256) prow[c] = 0.f;
    float sum = 0.f;
    for (int c = np + tid; c <= r; c += 256) {
        float e = __expf(prow[c] - m);
        prow[c] = e;
        sum += e;
    }
    red[tid] = sum; __syncthreads();
    for (int s = 128; s > 0; s >>= 1) {
        if (tid < s) red[tid] += red[tid + s];
        __syncthreads();
    }
    const float inv = 1.0f / red[0];
    __syncthreads();   // all e-values and zeros visible before permuting pass

    // Final pass: thread owns columns [16*tid, 16*tid+16). In-register
    // involution permutation + normalize + round. Zeros stay zero.
    {
        const int base = tid * 16;   // 256 * 16 = 4096 = TDIM
        float v[16];
        #pragma unroll
        for (int j = 0; j < 16; j += 4)
            *(float4*)&v[j] = *(const float4*)&prow[base + j];
        #pragma unroll
        for (int j = 0; j < 16; j++) v[j] = f2tf32f(v[j] * inv);
        #pragma unroll
        for (int a = 0; a < 4; a++) {
            float4 o = make_float4(v[a], v[4 + a], v[8 + a], v[12 + a]);
            *(float4*)&prow[base + 4 * a] = o;
        }
    }
}

// ---------------------------------------------------------------------------
// Kernel 4: y = P @ V (NT via g_vt, both t-permuted), K-range clipped,
// swizzled vectorized path.
// ---------------------------------------------------------------------------
__global__ __launch_bounds__(256, 2)
void k_gemm_pv(const int* __restrict__ n_padd_p, float* __restrict__ C)
{
    const int np = *n_padd_p;
    const int rm = blockIdx.y * BM;
    const int cn = blockIdx.x * BN;
    const int tid = threadIdx.x;
    const int lane = tid & 31, wid = tid >> 5;
    const int wm = wid & 1, wn = wid >> 1;
    const int g = lane >> 2, t4 = lane & 3;

    if (rm + BM <= np) {
        for (int idx = tid; idx < BM * (BN / 4); idx += 256) {
            int row = idx / (BN / 4);
            int c4 = idx % (BN / 4);
            ((float4*)(C + (size_t)(rm + row) * NF + cn))[c4] =
                make_float4(0.f, 0.f, 0.f, 0.f);
        }
        return;
    }

    const int kstart = np & ~(BK - 1);
    const int nk = (rm + BM - kstart) / BK;

    extern __shared__ float sm[];
    float* As[2] = { sm,               sm + BM * SW };
    float* Bs[2] = { sm + 2 * BM * SW, sm + 3 * BM * SW };

    float acc[16][4];
    #pragma unroll
    for (int i = 0; i < 16; i++)
        #pragma unroll
        for (int j = 0; j < 4; j++) acc[i][j] = 0.f;

    loadA_async_sw(As[0], g_P + (size_t)rm * TDIM + kstart, TDIM, tid);
    loadA_async_sw(Bs[0], g_vt + (size_t)cn * TDIM + kstart, TDIM, tid);
    CP_COMMIT();

    int buf = 0;
    for (int it = 0; it < nk; it++) {
        CP_WAIT0();
        __syncthreads();
        if (it + 1 < nk) {
            const int kn = kstart + (it + 1) * BK;
            loadA_async_sw(As[buf ^ 1], g_P + (size_t)rm * TDIM + kn, TDIM, tid);
            loadA_async_sw(Bs[buf ^ 1], g_vt + (size_t)cn * TDIM + kn, TDIM, tid);
            CP_COMMIT();
        }
        compute_NT_sw(As[buf], Bs[buf], acc, wm, wn, g, t4);
        buf ^= 1;
    }

    #pragma unroll
    for (int mt = 0; mt < 4; mt++) {
        #pragma unroll
        for (int nt = 0; nt < 4; nt++) {
            const int row = rm + wm * 64 + mt * 16 + g;
            const int col = cn + wn * 32 + nt * 8 + t4 * 2;
            *(float2*)(C + (size_t)row * NF + col) =
                make_float2(acc[mt*4+nt][0], acc[mt*4+nt][1]);
            *(float2*)(C + (size_t)(row + 8) * NF + col) =
                make_float2(acc[mt*4+nt][2], acc[mt*4+nt][3]);
        }
    }
}

// ---------------------------------------------------------------------------
extern "C" void kernel_launch(void* const* d_in, const int* in_sizes, int n_in,
                              void* d_out, int out_size)
{
    const float* x  = (const float*)d_in[0];
    const float* W  = (const float*)d_in[1];
    const float* b  = (const float*)d_in[2];
    const int*   np = (const int*)d_in[3];
    float* y = (float*)d_out;
    (void)in_sizes; (void)n_in; (void)out_size;

    const int smem_sw = 4 * (BM * SW) * (int)sizeof(float);   // 65536

    cudaFuncSetAttribute(k_gemm_qkv, cudaFuncAttributeMaxDynamicSharedMemorySize, smem_sw);
    cudaFuncSetAttribute(k_gemm_s,   cudaFuncAttributeMaxDynamicSharedMemorySize, smem_sw);
    cudaFuncSetAttribute(k_gemm_pv,  cudaFuncAttributeMaxDynamicSharedMemorySize, smem_sw);

    float* xr; float* wt;
    cudaGetSymbolAddress((void**)&xr, g_xr);
    cudaGetSymbolAddress((void**)&wt, g_wt);

    dim3 t(256);
    k_round_perm<<<1024, t>>>(x, xr, TDIM, CDIM);
    k_transpose_round_perm<<<dim3(N3 / 32, CDIM / 32), t>>>(W, wt);
    k_gemm_qkv<<<dim3(N3 / BN, TDIM / BM), t, smem_sw>>>(b);
    k_transpose_v<<<dim3(NF / 32, TDIM / 32), t>>>();
    k_gemm_s<<<dim3(TDIM / BN, TDIM / BM), t, smem_sw>>>(np);
    k_softmax<<<TDIM, t>>>(np);
    k_gemm_pv<<<dim3(NF / BN, TDIM / BM), t, smem_sw>>>(np, y);
}